// round 8
// baseline (speedup 1.0000x reference)
#include <cuda_runtime.h>
#include <math_constants.h>

// ChamferDistance: x (8,8192,3) f32, y (8,8192,3) f32 -> scalar f32.
// R8: FUSED single pass. D[q,r] = qq + rr - 2*dot computed ONCE (537M values
// instead of 1.07G): row-mins feed x->y, col-mins feed y->x.
//   per 2 distances (query pair packed f32x2, one ref):
//     s = add.f32x2(rr2, qq2); 3x fma.f32x2 -> full d^2 pair; 4 FMNMX.
// 2D tiling: ty(8) query-groups x tx(16) ref-groups; thread = 8q x 8r per tile.
// Col-mins: per-tile smem tree over ty + atomicMin (int min == float min for
// positive floats; exact, deterministic). Row-mins: once-per-block combine.

#define BATCH   8
#define NPTS    8192
#define RSPLIT  4
#define TPB     128
#define QT      64                             // queries per block (8 ty * 8)
#define RT      128                            // refs per tile (16 tx * 8)
#define QTILES  (NPTS / QT)                    // 128
#define RCHUNK  (NPTS / RSPLIT)                // 2048
#define NTILES  (RCHUNK / RT)                  // 16
#define EPS_F   1e-10f
#define POS_INF_BITS 0x7F800000

__device__ int   g_row[BATCH][NPTS];
__device__ int   g_col[BATCH][NPTS];
__device__ float g_partial[16];

__device__ __forceinline__ unsigned long long f2_fma(unsigned long long a, unsigned long long b, unsigned long long c) {
    unsigned long long d;
    asm("fma.rn.f32x2 %0, %1, %2, %3;" : "=l"(d) : "l"(a), "l"(b), "l"(c));
    return d;
}
__device__ __forceinline__ unsigned long long f2_add(unsigned long long a, unsigned long long b) {
    unsigned long long d;
    asm("add.rn.f32x2 %0, %1, %2;" : "=l"(d) : "l"(a), "l"(b));
    return d;
}
__device__ __forceinline__ unsigned long long f2_pack(float a, float b) {
    unsigned long long r;
    asm("mov.b64 %0, {%1, %2};" : "=l"(r) : "f"(a), "f"(b));
    return r;
}
__device__ __forceinline__ void f2_unpack(unsigned long long v, float& lo, float& hi) {
    asm("mov.b64 {%0, %1}, %2;" : "=f"(lo), "=f"(hi) : "l"(v));
}

__global__ void chamfer_init_kernel() {
    int idx = blockIdx.x * 256 + threadIdx.x;          // 512*256 = 131072
    if (idx < BATCH * NPTS) ((int*)g_row)[idx] = POS_INF_BITS;
    else ((int*)g_col)[idx - BATCH * NPTS] = POS_INF_BITS;
}

__global__ __launch_bounds__(TPB, 6)
void chamfer_pass_kernel(const float* __restrict__ x, const float* __restrict__ y) {
    const int qtile = blockIdx.x;
    const int rchk  = blockIdx.y;
    const int b     = blockIdx.z;
    const int tid   = threadIdx.x;
    const int tx    = tid & 15;                  // ref group 0..15
    const int ty    = tid >> 4;                  // query group 0..7

    // sm_ref: per tile, 128 refs pre-splatted: [i(8)][half(2)][g(16) x 16B]
    //   half0 = (rx,rx,ry,ry), half1 = (rz,rz,rr,rr). i stride 512B, g stride 16B.
    __shared__ float sm_ref[8 * 2 * 64];
    __shared__ float sm_red[TPB * 8];            // 1024 floats (col partials / row combine)

    // Load this thread's 8 queries, pack pairs: lanes (2p, 2p+1).
    unsigned long long qx2[4], qy2[4], qz2[4], qq2[4];
    float rowmin[8];
    const int qbase = qtile * QT;
#pragma unroll
    for (int p = 0; p < 4; p++) {
        const float* p0 = x + ((size_t)b * NPTS + qbase + ty * 8 + 2 * p) * 3;
        float a0 = p0[0], c0 = p0[1], e0 = p0[2];
        float a1 = p0[3], c1 = p0[4], e1 = p0[5];
        qq2[p] = f2_pack(a0 * a0 + c0 * c0 + e0 * e0, a1 * a1 + c1 * c1 + e1 * e1);
        qx2[p] = f2_pack(-2.0f * a0, -2.0f * a1);
        qy2[p] = f2_pack(-2.0f * c0, -2.0f * c1);
        qz2[p] = f2_pack(-2.0f * e0, -2.0f * e1);
        rowmin[2 * p] = CUDART_INF_F;
        rowmin[2 * p + 1] = CUDART_INF_F;
    }

    const float* __restrict__ Rb = y + (size_t)b * NPTS * 3;
    const int rbase0 = rchk * RCHUNK;

#pragma unroll 1
    for (int tile = 0; tile < NTILES; tile++) {
        __syncthreads();
        {   // Stage ref r = tid, pre-splatted (no MOVs in inner loop).
            const float* rp = Rb + (size_t)(rbase0 + tile * RT + tid) * 3;
            float rx = rp[0], ry = rp[1], rz = rp[2];
            float rr = rx * rx + ry * ry + rz * rz;
            int g = tid >> 3, i = tid & 7;
            float* d0 = &sm_ref[i * 128 + g * 4];
            d0[0] = rx; d0[1] = rx; d0[2] = ry; d0[3] = ry;
            float* d1 = d0 + 64;
            d1[0] = rz; d1[1] = rz; d1[2] = rr; d1[3] = rr;
        }
        __syncthreads();

        float colv[8];
#pragma unroll
        for (int i = 0; i < 8; i++) {
            // (rx,rx),(ry,ry) and (rz,rz),(rr,rr): two LDS.128, conflict-free spread.
            ulonglong2 A = *reinterpret_cast<const ulonglong2*>(&sm_ref[i * 128 + tx * 4]);
            ulonglong2 B = *reinterpret_cast<const ulonglong2*>(&sm_ref[i * 128 + 64 + tx * 4]);
            float cl = CUDART_INF_F;
#pragma unroll
            for (int p = 0; p < 4; p++) {
                unsigned long long acc = f2_add(B.y, qq2[p]);     // qq + rr
                acc = f2_fma(qx2[p], A.x, acc);
                acc = f2_fma(qy2[p], A.y, acc);
                acc = f2_fma(qz2[p], B.x, acc);                   // full d^2, 2 lanes
                float lo, hi;
                f2_unpack(acc, lo, hi);
                rowmin[2 * p]     = fminf(rowmin[2 * p], lo);
                rowmin[2 * p + 1] = fminf(rowmin[2 * p + 1], hi);
                cl = fminf(cl, fminf(lo, hi));
            }
            colv[i] = cl;
        }

        // Column-min combine over ty (8 partials per ref), then global int-min.
#pragma unroll
        for (int i = 0; i < 8; i++) sm_red[ty * 128 + tx * 8 + i] = colv[i];
        __syncthreads();
        {
            float v = sm_red[tid];
#pragma unroll
            for (int yy = 1; yy < 8; yy++) v = fminf(v, sm_red[yy * 128 + tid]);
            atomicMin(&g_col[b][rbase0 + tile * RT + tid], __float_as_int(v));
        }
    }

    // Row-min combine over tx (16 partials per query), once per block.
    __syncthreads();
#pragma unroll
    for (int u = 0; u < 8; u++) sm_red[tx * 64 + ty * 8 + u] = rowmin[u];
    __syncthreads();
    if (tid < QT) {
        float v = sm_red[tid];
#pragma unroll
        for (int xx = 1; xx < 16; xx++) v = fminf(v, sm_red[xx * 64 + tid]);
        atomicMin(&g_row[b][qbase + tid], __float_as_int(v));
    }
}

// 16 blocks: side(2) x batch(8). side 0 = rows (x->y), side 1 = cols (y->x).
__global__ __launch_bounds__(256)
void chamfer_reduce_kernel() {
    const int side = blockIdx.x >> 3;
    const int b    = blockIdx.x & 7;
    const int t    = threadIdx.x;
    const int* arr = side ? g_col[b] : g_row[b];

    float s = 0.0f;
#pragma unroll 4
    for (int n = t; n < NPTS; n += 256)
        s += sqrtf(__int_as_float(arr[n]) + EPS_F);

    __shared__ float red[256];
    red[t] = s;
    __syncthreads();
    for (int o = 128; o > 0; o >>= 1) {
        if (t < o) red[t] += red[t + o];
        __syncthreads();
    }
    if (t == 0) g_partial[blockIdx.x] = red[0];
}

__global__ void chamfer_final_kernel(float* __restrict__ out) {
    float s = 0.0f;
#pragma unroll
    for (int b = 0; b < BATCH; b++)
        s += fmaxf(g_partial[b], g_partial[8 + b]) * (1.0f / (float)NPTS);
    *out = s;
}

extern "C" void kernel_launch(void* const* d_in, const int* in_sizes, int n_in,
                              void* d_out, int out_size) {
    const float* x = (const float*)d_in[0];
    const float* y = (const float*)d_in[1];
    float* out = (float*)d_out;

    chamfer_init_kernel<<<512, 256>>>();
    dim3 grid(QTILES, RSPLIT, BATCH);            // 128 x 4 x 8 = 4096 blocks
    chamfer_pass_kernel<<<grid, TPB>>>(x, y);
    chamfer_reduce_kernel<<<16, 256>>>();
    chamfer_final_kernel<<<1, 1>>>(out);
}

// round 9
// speedup vs baseline: 1.6193x; 1.6193x over previous
#include <cuda_runtime.h>
#include <math_constants.h>

// ChamferDistance: x (8,8192,3) f32, y (8,8192,3) f32 -> scalar f32.
// FMA-pipe bound brute force with packed fma.rn.f32x2 (FFMA2).
//   d^2(q,r) = qq + (rr - 2*dot(q,r)); queries pre-scaled by -2; qq added in reduce.
//   min(sqrt(v+EPS)) == sqrt(min(v)+EPS) -> one sqrt per point at the end.
// R9: R7 inner loop (U=8: crossbar at 67% -> not binding) + tail fix:
// RSPLIT=32 -> 4096 blocks over 888 concurrent (6/SM, regs~78) = 4.6 waves
// -> ~92% tail efficiency (vs 2.3 waves / 77% in R7).

#define BATCH   8
#define NPTS    8192
#define RSPLIT  32
#define TPB     128
#define U       8                              // queries per thread
#define QPB     (TPB * U)                      // 1024 queries per block
#define QBLK    (BATCH * NPTS / QPB)           // 64
#define TR      128                            // reference points per smem tile
#define RCHUNK  (NPTS / RSPLIT)                // 256
#define NTILES  (RCHUNK / TR)                  // 2
#define EPS_F   1e-10f

__device__ float g_minpart[2][RSPLIT][BATCH * NPTS];
__device__ float g_partial[128];

__device__ __forceinline__ unsigned long long f2_fma(unsigned long long a, unsigned long long b, unsigned long long c) {
    unsigned long long d;
    asm("fma.rn.f32x2 %0, %1, %2, %3;" : "=l"(d) : "l"(a), "l"(b), "l"(c));
    return d;
}
__device__ __forceinline__ unsigned long long f2_pack(float a, float b) {
    unsigned long long r;
    asm("mov.b64 %0, {%1, %2};" : "=l"(r) : "f"(a), "f"(b));
    return r;
}
__device__ __forceinline__ void f2_unpack(unsigned long long v, float& lo, float& hi) {
    asm("mov.b64 {%0, %1}, %2;" : "=f"(lo), "=f"(hi) : "l"(v));
}

__global__ __launch_bounds__(TPB, 6)
void chamfer_pass_kernel(const float* __restrict__ x, const float* __restrict__ y) {
    const int dir = blockIdx.z;
    const float* __restrict__ Q = dir ? y : x;   // query side
    const float* __restrict__ R = dir ? x : y;   // reference side

    const int qbase = blockIdx.x * QPB;          // within one batch (8 blocks/batch)
    const int b     = qbase / NPTS;
    const int r0    = blockIdx.y * RCHUNK;
    const int t     = threadIdx.x;

    // Pair-interleaved tile: for ref pair j (points 2j, 2j+1):
    //   sm[8j+0..1]=x pair, [8j+2..3]=y pair, [8j+4..5]=z pair, [8j+6..7]=rr pair
    __shared__ float sm[TR * 4];

    float minv[U];
    unsigned long long qx2[U], qy2[U], qz2[U];   // query coords pre-scaled by -2, splatted
#pragma unroll
    for (int u = 0; u < U; u++) {
        const float* p = Q + (size_t)(qbase + u * TPB + t) * 3;
        float a = p[0] * -2.0f, c = p[1] * -2.0f, e = p[2] * -2.0f;
        qx2[u] = f2_pack(a, a);
        qy2[u] = f2_pack(c, c);
        qz2[u] = f2_pack(e, e);
        minv[u] = CUDART_INF_F;
    }

    const float* __restrict__ Rb = R + (size_t)b * NPTS * 3;
    const int jj = (t >> 1) * 8 + (t & 1);       // interleave slot for this thread's ref point

#pragma unroll 1
    for (int tile = 0; tile < NTILES; tile++) {
        __syncthreads();
        {
            const float* rp = Rb + (size_t)(r0 + tile * TR + t) * 3;   // TR == TPB
            float rx = rp[0], ry = rp[1], rz = rp[2];
            sm[jj + 0] = rx;
            sm[jj + 2] = ry;
            sm[jj + 4] = rz;
            sm[jj + 6] = rx * rx + ry * ry + rz * rz;
        }
        __syncthreads();

#pragma unroll 4
        for (int j = 0; j < TR / 2; j++) {
            // Two LDS.128 -> four pre-packed f32x2 operands (broadcast, conflict-free),
            // each pair reused by 8 queries -> crossbar at ~67% of capacity.
            ulonglong2 A  = *reinterpret_cast<const ulonglong2*>(&sm[8 * j]);      // {x-pair, y-pair}
            ulonglong2 Bv = *reinterpret_cast<const ulonglong2*>(&sm[8 * j + 4]);  // {z-pair, rr-pair}
#pragma unroll
            for (int u = 0; u < U; u++) {
                unsigned long long acc = f2_fma(qx2[u], A.x, Bv.y);  // rr - 2 qx rx
                acc = f2_fma(qy2[u], A.y, acc);
                acc = f2_fma(qz2[u], Bv.x, acc);                     // rr - 2 dot (packed x2)
                float lo, hi;
                f2_unpack(acc, lo, hi);
                minv[u] = fminf(minv[u], fminf(lo, hi));
            }
        }
    }

#pragma unroll
    for (int u = 0; u < U; u++) {
        g_minpart[dir][blockIdx.y][qbase + u * TPB + t] = minv[u];
    }
}

// 128 blocks: dir(2) x batch(8) x chunk(8); each covers 1024 queries.
// Adds the deferred qq term before the sqrt.
__global__ __launch_bounds__(256)
void chamfer_reduce_kernel(const float* __restrict__ x, const float* __restrict__ y) {
    const int dir   = blockIdx.x >> 6;
    const int b     = (blockIdx.x >> 3) & 7;
    const int chunk = blockIdx.x & 7;
    const int t     = threadIdx.x;
    const float* __restrict__ Qside = dir ? y : x;

    float s = 0.0f;
#pragma unroll
    for (int k = 0; k < 4; k++) {
        const int q = b * NPTS + chunk * 1024 + k * 256 + t;
        float v = g_minpart[dir][0][q];
#pragma unroll
        for (int r = 1; r < RSPLIT; r++) v = fminf(v, g_minpart[dir][r][q]);
        const float* p = Qside + (size_t)q * 3;
        float qq = p[0] * p[0] + p[1] * p[1] + p[2] * p[2];
        s += sqrtf(v + qq + EPS_F);
    }

    __shared__ float red[256];
    red[t] = s;
    __syncthreads();
    for (int o = 128; o > 0; o >>= 1) {
        if (t < o) red[t] += red[t + o];
        __syncthreads();
    }
    if (t == 0) g_partial[blockIdx.x] = red[0];
}

__global__ void chamfer_final_kernel(float* __restrict__ out) {
    float s = 0.0f;
#pragma unroll
    for (int b = 0; b < BATCH; b++) {
        float m0 = 0.0f, m1 = 0.0f;
#pragma unroll
        for (int c = 0; c < 8; c++) {
            m0 += g_partial[(0 << 6) | (b << 3) | c];
            m1 += g_partial[(1 << 6) | (b << 3) | c];
        }
        s += fmaxf(m0, m1) * (1.0f / (float)NPTS);
    }
    *out = s;
}

extern "C" void kernel_launch(void* const* d_in, const int* in_sizes, int n_in,
                              void* d_out, int out_size) {
    const float* x = (const float*)d_in[0];
    const float* y = (const float*)d_in[1];
    float* out = (float*)d_out;

    dim3 grid(QBLK, RSPLIT, 2);                  // 64 x 32 x 2 = 4096 blocks
    chamfer_pass_kernel<<<grid, TPB>>>(x, y);
    chamfer_reduce_kernel<<<128, 256>>>(x, y);
    chamfer_final_kernel<<<1, 1>>>(out);
}